// round 9
// baseline (speedup 1.0000x reference)
#include <cuda_runtime.h>
#include <cuda_fp16.h>
#include <cstddef>

#define NB     2
#define N_IN   163842
#define N_OUT  40962
#define CDIM   128
#define KCAND  7

// Scratch (static device globals — no runtime allocation).
__device__ __half g_down_h[(size_t)NB * N_OUT * CDIM];   // 21 MB
__device__ float  g_denom[N_OUT];

// ---------------------------------------------------------------------------
// Zero one batch-half of the fp16 scratch; batch 0 also zeroes denom.
// Grid-stride streaming stores.
// ---------------------------------------------------------------------------
__global__ void __launch_bounds__(256) zero_half_kernel(int batch) {
    const size_t half16 = (size_t)N_OUT * CDIM * sizeof(__half) / 16;  // uint4s
    uint4* base = reinterpret_cast<uint4*>(
        g_down_h + (size_t)batch * N_OUT * CDIM);
    const size_t stride = (size_t)gridDim.x * blockDim.x;
    uint4 z; z.x = 0u; z.y = 0u; z.z = 0u; z.w = 0u;
    for (size_t i = (size_t)blockIdx.x * blockDim.x + threadIdx.x;
         i < half16; i += stride) {
        base[i] = z;
    }
    if (batch == 0) {
        for (size_t t = (size_t)blockIdx.x * blockDim.x + threadIdx.x;
             t < N_OUT; t += stride) {
            g_denom[t] = 0.f;
        }
    }
}

// ---------------------------------------------------------------------------
// Scatter for ONE batch. One warp handles TWO input rows:
//   lanes 0-15 -> row 2*warp, lanes 16-31 -> row 2*warp+1.
// Each lane covers 8 channels (32B f32 in, 16B fp16 red out):
//   2x LDG.128 + pack + red.global.add.noftz.v4.f16x2.
// Per (row,batch): 16 REDG lane-ops — identical to the fused R8 scatter.
// do_denom: only the b=0 pass accumulates denom (batch-invariant).
// ---------------------------------------------------------------------------
__global__ void __launch_bounds__(256) scatter_kernel(
        const float* __restrict__ x,
        const float* __restrict__ omega,
        const int*   __restrict__ parent,
        int batch, int do_denom) {
    const int warp = (int)(((size_t)blockIdx.x * blockDim.x + threadIdx.x) >> 5);
    const int lane = threadIdx.x & 31;
    const int row  = warp * 2 + (lane >> 4);
    if (row >= N_IN) return;

    const int   p  = parent[row];   // 2-way broadcast per half-warp
    const float om = omega[row];

    const int li = lane & 15;       // 32B slot (8 channels) within the row

    const float4* xr =
        reinterpret_cast<const float4*>(x + ((size_t)batch * N_IN + row) * CDIM)
        + li * 2;
    float4 a = xr[0];
    float4 b = xr[1];
    a.x *= om; a.y *= om; a.z *= om; a.w *= om;
    b.x *= om; b.y *= om; b.z *= om; b.w *= om;

    __half2 h0 = __floats2half2_rn(a.x, a.y);
    __half2 h1 = __floats2half2_rn(a.z, a.w);
    __half2 h2 = __floats2half2_rn(b.x, b.y);
    __half2 h3 = __floats2half2_rn(b.z, b.w);

    __half* dst = g_down_h + ((size_t)batch * N_OUT + p) * CDIM + li * 8;
    asm volatile("red.global.add.noftz.v4.f16x2 [%0], {%1, %2, %3, %4};"
                 :: "l"(dst),
                    "r"(*reinterpret_cast<unsigned*>(&h0)),
                    "r"(*reinterpret_cast<unsigned*>(&h1)),
                    "r"(*reinterpret_cast<unsigned*>(&h2)),
                    "r"(*reinterpret_cast<unsigned*>(&h3))
                 : "memory");

    if (do_denom && li == 0) {
        atomicAdd(&g_denom[p], om);
    }
}

// ---------------------------------------------------------------------------
// Gather for ONE batch. One warp handles TWO input rows (one per half-warp).
// Weight phase: lanes 0-6 serve row A's candidates, lanes 16-22 row B's
// (3 scalar LDG + 1 MUFU per candidate), width-8 butterfly per group,
// denom folded in, clamped, packed to half2.
// Accumulation: lane (lane&15) covers 16B = 8 halves of its row per
// candidate; per warp per k: 2 SHFL + 1 LDG.128 + 4 HFMA2 into dual
// interleaved fp16 partials (chains <= 4), f32 finalize + 2x STG.128.
// ---------------------------------------------------------------------------
__global__ void __launch_bounds__(256) gather_kernel(
        const float* __restrict__ delta,
        const float* __restrict__ mask,
        const int*   __restrict__ cand,
        float*       __restrict__ out,
        int batch) {
    const int warp = (int)(((size_t)blockIdx.x * blockDim.x + threadIdx.x) >> 5);
    const int lane = threadIdx.x & 31;
    const int row  = warp * 2 + (lane >> 4);
    if (row >= N_IN) return;

    const float INV2S2 = 3.125f;  // 1 / (2 * 0.4^2)
    const int kidx = lane & 15;

    // ---- weights: lanes {0-6} and {16-22}, one candidate each ----
    float w = 0.f;
    int   c = 0;
    if (kidx < KCAND) {
        const size_t o = (size_t)row * KCAND + kidx;
        const float d = delta[o];
        const float m = mask[o];
        c = cand[o];
        w = __expf(-d * d * INV2S2) * m;
    }
    // width-8 butterfly: groups {0-7} and {16-23} reduce independently
    float s = w;
    s += __shfl_down_sync(0xffffffffu, s, 4, 8);
    s += __shfl_down_sync(0xffffffffu, s, 2, 8);
    s += __shfl_down_sync(0xffffffffu, s, 1, 8);
    s  = __shfl_sync(0xffffffffu, s, 0, 8);   // group base broadcasts

    unsigned whbits = 0;
    if (kidx < KCAND) {
        const float den = fmaxf(__ldg(&g_denom[c]), 1e-8f);
        float wf = w / (fmaxf(s, 1e-8f) * den);
        // Clamp: zero-parent outputs give wf ~ 1e8 -> fp16 inf -> inf*0 NaN.
        // Their rows are all-zero, so any finite weight is exact.
        wf = fminf(wf, 1000.0f);
        const __half2 wh = __float2half2_rn(wf);
        whbits = *reinterpret_cast<const unsigned*>(&wh);
    }

    // ---- accumulation: half-warp covers its row's 256B fp16 ----
    const int li = lane & 15;
    const int hw = lane & 16;   // half-warp base for shuffles

    const __half2 hz = __float2half2_rn(0.f);
    __half2 accA[4] = {hz, hz, hz, hz};
    __half2 accB[4] = {hz, hz, hz, hz};

#pragma unroll
    for (int k = 0; k < KCAND; ++k) {
        const unsigned wb = __shfl_sync(0xffffffffu, whbits, hw | k);
        const int      ik = __shfl_sync(0xffffffffu, c, hw | k);
        const __half2  wh = *reinterpret_cast<const __half2*>(&wb);
        const float4 raw = __ldg(reinterpret_cast<const float4*>(
            g_down_h + ((size_t)batch * N_OUT + ik) * CDIM) + li);
        const __half2* h2 = reinterpret_cast<const __half2*>(&raw);
        if ((k & 1) == 0) {
#pragma unroll
            for (int j = 0; j < 4; ++j) accA[j] = __hfma2(h2[j], wh, accA[j]);
        } else {
#pragma unroll
            for (int j = 0; j < 4; ++j) accB[j] = __hfma2(h2[j], wh, accB[j]);
        }
    }

    float res[8];
#pragma unroll
    for (int j = 0; j < 4; ++j) {
        const float2 a = __half22float2(accA[j]);
        const float2 b = __half22float2(accB[j]);
        res[2 * j]     = a.x + b.x;
        res[2 * j + 1] = a.y + b.y;
    }

    float* dst = out + ((size_t)batch * N_IN + row) * CDIM + li * 8;
    reinterpret_cast<float4*>(dst)[0] = make_float4(res[0], res[1], res[2], res[3]);
    reinterpret_cast<float4*>(dst)[1] = make_float4(res[4], res[5], res[6], res[7]);
}

// ---------------------------------------------------------------------------
// Launcher: batch-split two-stream pipeline.
//   main: zero0(+denom) -> scat0(+denom) -> [evS0] -> gath0 -> wait(evJoin)
//   s2:   wait(fork) -> zero1 -> wait(evS0) -> scat1 -> gath1 -> [evJoin]
// scat1 (HBM-read bound) is deliberately staggered under gath0 (LTS bound).
// Stream/event creation is host-side only (no device memory).
// ---------------------------------------------------------------------------
extern "C" void kernel_launch(void* const* d_in, const int* in_sizes, int n_in,
                              void* d_out, int out_size) {
    const float* x      = (const float*)d_in[0];
    const float* omega  = (const float*)d_in[1];
    const float* delta  = (const float*)d_in[2];
    const float* mask   = (const float*)d_in[3];
    const int*   parent = (const int*)d_in[4];
    const int*   cand   = (const int*)d_in[5];
    float*       out    = (float*)d_out;

    (void)in_sizes; (void)n_in; (void)out_size;

    const int ZBLK = 1024;
    const int WARPS = (N_IN + 1) / 2;           // 2 rows per warp
    const int BLKS  = (WARPS + 8 - 1) / 8;      // 8 warps per block

    cudaStream_t s2;
    cudaStreamCreateWithFlags(&s2, cudaStreamNonBlocking);
    cudaEvent_t evFork, evS0, evJoin;
    cudaEventCreateWithFlags(&evFork, cudaEventDisableTiming);
    cudaEventCreateWithFlags(&evS0,   cudaEventDisableTiming);
    cudaEventCreateWithFlags(&evJoin, cudaEventDisableTiming);

    // Fork s2 off the capture origin.
    cudaEventRecord(evFork, 0);
    cudaStreamWaitEvent(s2, evFork, 0);

    // Phase 0: zero both halves concurrently.
    zero_half_kernel<<<ZBLK, 256, 0, 0>>>(0);
    zero_half_kernel<<<ZBLK, 256, 0, s2>>>(1);

    // Main: scatter b=0 (+denom), then gather b=0.
    scatter_kernel<<<BLKS, 256, 0, 0>>>(x, omega, parent, 0, 1);
    cudaEventRecord(evS0, 0);
    gather_kernel<<<BLKS, 256, 0, 0>>>(delta, mask, cand, out, 0);

    // s2: stagger scatter b=1 under gather b=0, then gather b=1.
    cudaStreamWaitEvent(s2, evS0, 0);
    scatter_kernel<<<BLKS, 256, 0, s2>>>(x, omega, parent, 1, 0);
    gather_kernel<<<BLKS, 256, 0, s2>>>(delta, mask, cand, out, 1);
    cudaEventRecord(evJoin, s2);

    // Join back to the origin stream.
    cudaStreamWaitEvent(0, evJoin, 0);
}

// round 10
// speedup vs baseline: 1.1457x; 1.1457x over previous
#include <cuda_runtime.h>
#include <cuda_fp16.h>
#include <cstddef>

#define NB     2
#define N_IN   163842
#define N_OUT  40962
#define CDIM   128
#define KCAND  7

// Scratch (static device globals — no runtime allocation).
// Pooled weighted sums accumulate directly in fp16 (atomic f16x2 reductions).
__device__ __half g_down_h[(size_t)NB * N_OUT * CDIM];   // 21 MB
__device__ float  g_denom[N_OUT];

// ---------------------------------------------------------------------------
// Kernel 0: zero fp16 scratch + denom (graph-replayed every run). Grid-stride.
// ---------------------------------------------------------------------------
__global__ void __launch_bounds__(256) zero_kernel() {
    const size_t total16 = (size_t)NB * N_OUT * CDIM * sizeof(__half) / 16;
    const size_t stride  = (size_t)gridDim.x * blockDim.x;
    for (size_t i = (size_t)blockIdx.x * blockDim.x + threadIdx.x;
         i < total16; i += stride) {
        uint4 z; z.x = 0u; z.y = 0u; z.z = 0u; z.w = 0u;
        reinterpret_cast<uint4*>(g_down_h)[i] = z;
    }
    const size_t t = (size_t)blockIdx.x * blockDim.x + threadIdx.x;
    if (t < N_OUT) g_denom[t] = 0.f;
}

// ---------------------------------------------------------------------------
// Kernel 1: scatter-add in fp16 (identical to the 96.7us R8 version):
//   down_h[b, parent[n], :] += fp16(omega[n] * x[b, n, :])
//   denom[parent[n]]        += omega[n]
// One warp per input row n; lanes 0-15 -> b=0, lanes 16-31 -> b=1; each lane
// covers 8 channels: 2x LDG.128 + pack + red.global.add.noftz.v4.f16x2.
// ---------------------------------------------------------------------------
__global__ void __launch_bounds__(256) scatter_kernel(
        const float* __restrict__ x,
        const float* __restrict__ omega,
        const int*   __restrict__ parent) {
    const int warp = (int)(((size_t)blockIdx.x * blockDim.x + threadIdx.x) >> 5);
    const int lane = threadIdx.x & 31;
    if (warp >= N_IN) return;

    const int   p  = parent[warp];   // broadcast
    const float om = omega[warp];    // broadcast

    const int sub = lane >> 4;       // batch
    const int li  = lane & 15;       // 16B slot (8 channels) within the row

    const float4* xr =
        reinterpret_cast<const float4*>(x + ((size_t)sub * N_IN + warp) * CDIM)
        + li * 2;
    float4 a = xr[0];
    float4 b = xr[1];
    a.x *= om; a.y *= om; a.z *= om; a.w *= om;
    b.x *= om; b.y *= om; b.z *= om; b.w *= om;

    __half2 h0 = __floats2half2_rn(a.x, a.y);
    __half2 h1 = __floats2half2_rn(a.z, a.w);
    __half2 h2 = __floats2half2_rn(b.x, b.y);
    __half2 h3 = __floats2half2_rn(b.z, b.w);

    __half* dst = g_down_h + ((size_t)sub * N_OUT + p) * CDIM + li * 8;
    asm volatile("red.global.add.noftz.v4.f16x2 [%0], {%1, %2, %3, %4};"
                 :: "l"(dst),
                    "r"(*reinterpret_cast<unsigned*>(&h0)),
                    "r"(*reinterpret_cast<unsigned*>(&h1)),
                    "r"(*reinterpret_cast<unsigned*>(&h2)),
                    "r"(*reinterpret_cast<unsigned*>(&h3))
                 : "memory");

    if (lane == 0) {
        atomicAdd(&g_denom[p], om);
    }
}

// ---------------------------------------------------------------------------
// Kernel 2: gather. One warp per input row n.
// Weights lane-parallel (lanes 0-6), width-8 butterfly, denom folded, clamp,
// pack to half2 — same as R8.
// NEW: all 7 candidate row-loads are issued BACK-TO-BACK into a register
// staging array before any consumption (MLP_p1 = 7), hiding the ~234-262cyc
// L2 latency that the profile shows is the real bound (L2=46%, issue=40%,
// nothing saturated). Accumulation afterwards: dual interleaved HFMA2
// partials, f32 finalize.
// ---------------------------------------------------------------------------
__global__ void __launch_bounds__(256) gather_kernel(
        const float* __restrict__ delta,
        const float* __restrict__ mask,
        const int*   __restrict__ cand,
        float*       __restrict__ out) {
    const int warp = (int)(((size_t)blockIdx.x * blockDim.x + threadIdx.x) >> 5);
    const int lane = threadIdx.x & 31;
    if (warp >= N_IN) return;

    const float INV2S2 = 3.125f;  // 1 / (2 * 0.4^2)

    // ---- lanes 0-6: per-candidate weight ----
    float w = 0.f;
    int   c = 0;
    if (lane < KCAND) {
        const size_t o = (size_t)warp * KCAND + lane;
        const float d = delta[o];
        const float m = mask[o];
        c = cand[o];
        w = __expf(-d * d * INV2S2) * m;
    }
    // sum over lanes 0-7 (lane 7 contributes 0), width-8 butterfly
    float s = w;
    s += __shfl_down_sync(0xffffffffu, s, 4, 8);
    s += __shfl_down_sync(0xffffffffu, s, 2, 8);
    s += __shfl_down_sync(0xffffffffu, s, 1, 8);
    s  = __shfl_sync(0xffffffffu, s, 0, 8);   // lanes 0-7 get total

    unsigned whbits = 0;
    if (lane < KCAND) {
        const float den = fmaxf(__ldg(&g_denom[c]), 1e-8f);
        float wf = w / (fmaxf(s, 1e-8f) * den);
        // Clamp: zero-parent outputs give wf ~ 1e8 -> fp16 inf -> inf*0 NaN.
        // Their rows are all-zero, so any finite weight is exact.
        wf = fminf(wf, 1000.0f);
        const __half2 wh = __float2half2_rn(wf);
        whbits = *reinterpret_cast<const unsigned*>(&wh);
    }

    const int sub = lane >> 4;
    const int li  = lane & 15;

    // ---- stage: broadcast all indices, then issue ALL 7 loads ----
    int      iks[KCAND];
    unsigned wbs[KCAND];
#pragma unroll
    for (int k = 0; k < KCAND; ++k) {
        iks[k] = __shfl_sync(0xffffffffu, c, k);
        wbs[k] = __shfl_sync(0xffffffffu, whbits, k);
    }

    float4 raw[KCAND];
#pragma unroll
    for (int k = 0; k < KCAND; ++k) {
        raw[k] = __ldg(reinterpret_cast<const float4*>(
            g_down_h + ((size_t)sub * N_OUT + iks[k]) * CDIM) + li);
    }

    // ---- accumulate: dual interleaved fp16 partials (chains <= 4) ----
    const __half2 hz = __float2half2_rn(0.f);
    __half2 accA[4] = {hz, hz, hz, hz};
    __half2 accB[4] = {hz, hz, hz, hz};

#pragma unroll
    for (int k = 0; k < KCAND; ++k) {
        const __half2  wh = *reinterpret_cast<const __half2*>(&wbs[k]);
        const __half2* h2 = reinterpret_cast<const __half2*>(&raw[k]);
        if ((k & 1) == 0) {
#pragma unroll
            for (int j = 0; j < 4; ++j) accA[j] = __hfma2(h2[j], wh, accA[j]);
        } else {
#pragma unroll
            for (int j = 0; j < 4; ++j) accB[j] = __hfma2(h2[j], wh, accB[j]);
        }
    }

    // Finalize in f32: convert both partials, add, store.
    float res[8];
#pragma unroll
    for (int j = 0; j < 4; ++j) {
        const float2 a = __half22float2(accA[j]);
        const float2 b = __half22float2(accB[j]);
        res[2 * j]     = a.x + b.x;
        res[2 * j + 1] = a.y + b.y;
    }

    float* dst = out + ((size_t)sub * N_IN + warp) * CDIM + li * 8;
    reinterpret_cast<float4*>(dst)[0] = make_float4(res[0], res[1], res[2], res[3]);
    reinterpret_cast<float4*>(dst)[1] = make_float4(res[4], res[5], res[6], res[7]);
}

// ---------------------------------------------------------------------------
// Launcher. Input order: x, omega, delta, cand_mask, parent_idx, cand_idx.
// Output: float32 (B, N_IN, C). Single stream (two-stream split regressed).
// ---------------------------------------------------------------------------
extern "C" void kernel_launch(void* const* d_in, const int* in_sizes, int n_in,
                              void* d_out, int out_size) {
    const float* x      = (const float*)d_in[0];
    const float* omega  = (const float*)d_in[1];
    const float* delta  = (const float*)d_in[2];
    const float* mask   = (const float*)d_in[3];
    const int*   parent = (const int*)d_in[4];
    const int*   cand   = (const int*)d_in[5];
    float*       out    = (float*)d_out;

    (void)in_sizes; (void)n_in; (void)out_size;

    // Zero fp16 scratch + denom
    {
        const size_t total16 = (size_t)NB * N_OUT * CDIM * sizeof(__half) / 16;
        const int threads = 256;
        const int blocks  = (int)((total16 + threads - 1) / threads);
        zero_kernel<<<blocks, threads>>>();
    }
    // Scatter pool (fp16 vector reductions)
    {
        const int threads = 256;  // 8 warps / block
        const int blocks  = (N_IN + 8 - 1) / 8;
        scatter_kernel<<<blocks, threads>>>(x, omega, parent);
    }
    // Gather + weight (prefetched loads, fp16 HFMA2 accumulate, f32 finalize)
    {
        const int threads = 256;
        const int blocks  = (N_IN + 8 - 1) / 8;
        gather_kernel<<<blocks, threads>>>(delta, mask, cand, out);
    }
}